// round 9
// baseline (speedup 1.0000x reference)
#include <cuda_runtime.h>
#include <math.h>

#define TPB 64
#define NS 2
#define COLS (NS * TPB)
#define NPART 2048

__device__ float g_partials[NPART];
__device__ unsigned int g_count;

// One Sutherland-Hodgman clip pass for ONE stream. Polygon lives in a
// thread-private smem column of float2 ([slot][col], stride COLS ->
// conflict-free 64-bit accesses). Push = predicated STS.64 + pointer bump.
// In-place safe: all INCAP slots read into registers before any write.
// Reads of slots >= np are predicate-discarded; garbage is harmless.
// Reference semantics: keep = (val <= 0), crossing = strict sign change,
// frozen = empty result -> keep pre-clip polygon, stop clipping.
template <int INCAP>
__device__ __forceinline__ void clip_edge_smem(float a, float b, float c,
                                               float2* __restrict__ sp,
                                               int col, int& np, bool& frozen) {
    if (frozen || np <= 2) return;

    float2 r[INCAP];
    float v[INCAP];
#pragma unroll
    for (int j = 0; j < INCAP; j++) {
        r[j] = sp[j * COLS + col];
        v[j] = a * r[j].x + b * r[j].y + c;
    }

    float2* wp = sp + col;
    int nn = 0;
#pragma unroll
    for (int j = 0; j < INCAP; j++) {
        bool act  = (j < np);
        bool last = (j + 1 == np);
        const int j1 = (j + 1 < INCAP) ? (j + 1) : 0;
        float tv = last ? v[0]   : v[j1];
        float tx = last ? r[0].x : r[j1].x;
        float ty = last ? r[0].y : r[j1].y;

        bool keep = act && (v[j] <= 0.0f);
        bool crs  = act && (v[j] * tv < 0.0f);

        if (keep) {
            *wp = r[j];
            wp += COLS;
            nn++;
        }
        if (crs) {
            float a2 = ty - r[j].y;
            float b2 = r[j].x - tx;
            float c2 = tx * r[j].y - ty * r[j].x;
            float wd = a * b2 - b * a2;
            float iw = __fdividef(1.0f, wd);
            float2 ip;
            ip.x = (b * c2 - c * b2) * iw;
            ip.y = (c * a2 - a * c2) * iw;
            *wp = ip;
            wp += COLS;
            nn++;
        }
    }

    if (nn > 0) np = nn;  // geometric bound: nn <= INCAP+1 <= 8
    else frozen = true;   // keep old polygon (reference semantics)
}

__global__ void __launch_bounds__(TPB)
giou_kernel(const float* __restrict__ pred,
            const float* __restrict__ tgt,
            float* __restrict__ out, int n) {
    __shared__ float2 s_xy[8 * COLS];   // clip polygons (2 streams)
    __shared__ float2 c_xy[8 * COLS];   // corners: 0-3 pred, 4-7 tgt

    int t = threadIdx.x;
    int base = blockIdx.x * (NS * TPB);

    int   idx[NS];
    int   colv[NS];
    bool  act[NS];
    float area_sum[NS], uni_v[NS];
    float giou = 0.0f;

#pragma unroll
    for (int s = 0; s < NS; s++) {
        colv[s] = s * TPB + t;
        idx[s]  = base + colv[s];
        act[s]  = (idx[s] < n);
    }

    // ---- phase A: load boxes, build corners into smem, seed polygons ----
#pragma unroll
    for (int s = 0; s < NS; s++) {
        int col = colv[s];
        int i = act[s] ? idx[s] : 0;           // safe clamp for loads
        const float2* pb = (const float2*)(pred + 6 * i);
        const float2* tb = (const float2*)(tgt + 6 * i);
        float2 p0 = __ldg(pb), p1 = __ldg(pb + 1), p2 = __ldg(pb + 2);
        float2 t0 = __ldg(tb), t1 = __ldg(tb + 1), t2 = __ldg(tb + 2);
        area_sum[s] = p1.x * p1.y + t1.x * t1.y;

        {
            float rinv = rsqrtf(fmaf(p2.x, p2.x, p2.y * p2.y));
            float cth = p2.y * rinv, sth = p2.x * rinv;
            float hw = 0.5f * p1.x, hl = 0.5f * p1.y;
            float2 c0 = make_float2(p0.x - hw * cth - hl * sth, p0.y - hw * sth + hl * cth);
            float2 c1 = make_float2(p0.x - hw * cth + hl * sth, p0.y - hw * sth - hl * cth);
            float2 c2 = make_float2(p0.x + hw * cth + hl * sth, p0.y + hw * sth - hl * cth);
            float2 c3 = make_float2(p0.x + hw * cth - hl * sth, p0.y + hw * sth + hl * cth);
            c_xy[0 * COLS + col] = c0;  s_xy[0 * COLS + col] = c0;
            c_xy[1 * COLS + col] = c1;  s_xy[1 * COLS + col] = c1;
            c_xy[2 * COLS + col] = c2;  s_xy[2 * COLS + col] = c2;
            c_xy[3 * COLS + col] = c3;  s_xy[3 * COLS + col] = c3;
        }
        {
            float rinv = rsqrtf(fmaf(t2.x, t2.x, t2.y * t2.y));
            float cth = t2.y * rinv, sth = t2.x * rinv;
            float hw = 0.5f * t1.x, hl = 0.5f * t1.y;
            c_xy[4 * COLS + col] = make_float2(t0.x - hw * cth - hl * sth, t0.y - hw * sth + hl * cth);
            c_xy[5 * COLS + col] = make_float2(t0.x - hw * cth + hl * sth, t0.y - hw * sth - hl * cth);
            c_xy[6 * COLS + col] = make_float2(t0.x + hw * cth + hl * sth, t0.y + hw * sth - hl * cth);
            c_xy[7 * COLS + col] = make_float2(t0.x + hw * cth - hl * sth, t0.y + hw * sth + hl * cth);
        }
    }

    // ---- phase B: clip, edges outer / streams inner (interleaved chains) ----
    int  np_[NS]     = {4, 4};
    bool frozen_[NS] = {false, false};
#pragma unroll
    for (int e = 0; e < 4; e++) {
        const int e1 = (e + 1) & 3;
#pragma unroll
        for (int s = 0; s < NS; s++) {
            int col = colv[s];
            float2 P = c_xy[(4 + e) * COLS + col];
            float2 Q = c_xy[(4 + e1) * COLS + col];
            float a = Q.y - P.y;
            float b = P.x - Q.x;
            float c = Q.x * P.y - Q.y * P.x;
            if (e == 0)      clip_edge_smem<4>(a, b, c, s_xy, col, np_[s], frozen_[s]);
            else if (e == 1) clip_edge_smem<5>(a, b, c, s_xy, col, np_[s], frozen_[s]);
            else if (e == 2) clip_edge_smem<6>(a, b, c, s_xy, col, np_[s], frozen_[s]);
            else             clip_edge_smem<7>(a, b, c, s_xy, col, np_[s], frozen_[s]);
        }
    }

    // ---- phase C: shoelace + IoU per stream ----
#pragma unroll
    for (int s = 0; s < NS; s++) {
        int col = colv[s];
        int np = np_[s];
        float s2 = 0.0f;
        float2 q[8];
#pragma unroll
        for (int k = 0; k < 8; k++) q[k] = s_xy[k * COLS + col];
#pragma unroll
        for (int j = 0; j < 8; j++) {
            bool a8   = (j < np);
            bool last = (j + 1 == np);
            const int j1 = (j + 1) & 7;
            float nx = last ? q[0].x : q[j1].x;
            float ny = last ? q[0].y : q[j1].y;
            float tm = q[j].x * ny - q[j].y * nx;
            s2 += a8 ? tm : 0.0f;
        }
        float inter = (np > 2) ? 0.5f * fabsf(s2) : 0.0f;
        float uni = area_sum[s] - inter;
        float iou = inter * __fdividef(1.0f, uni + 1e-16f);
        uni_v[s] = uni;
        if (act[s]) out[idx[s]] = iou;
        giou += act[s] ? (1.0f - iou) : 0.0f;
    }

    // ---- phase D: convex hull area per stream (reference all-pairs form,
    //      antisymmetric: each unordered pair once, min/max trees) ----
#pragma unroll
    for (int s = 0; s < NS; s++) {
        int col = colv[s];
        float2 P[8];
#pragma unroll
        for (int k = 0; k < 8; k++) P[k] = c_xy[k * COLS + col];

        float hs = 0.0f;
#pragma unroll
        for (int ii = 0; ii < 8; ii++) {
            float dx[8], dy[8];
#pragma unroll
            for (int k = 0; k < 8; k++) {
                dx[k] = P[k].x - P[ii].x;
                dy[k] = P[k].y - P[ii].y;
            }
#pragma unroll
            for (int jj = ii + 1; jj < 8; jj++) {
                float ex = dx[jj], ey = dy[jj];
                float cr[6];
                int c6 = 0;
#pragma unroll
                for (int k = 0; k < 8; k++) {
                    if (k == ii || k == jj) continue;  // cross == 0 there
                    cr[c6++] = ex * dy[k] - ey * dx[k];
                }
                float mn = fminf(fminf(fminf(cr[0], cr[1]), fminf(cr[2], cr[3])),
                                 fminf(cr[4], cr[5]));
                float mx = fmaxf(fmaxf(fmaxf(cr[0], cr[1]), fmaxf(cr[2], cr[3])),
                                 fmaxf(cr[4], cr[5]));
                float len2 = ex * ex + ey * ey;
                bool okL = (len2 > 1e-12f) && (mn >= -1e-6f);  // ii -> jj
                bool okR = (len2 > 1e-12f) && (mx <= 1e-6f);   // jj -> ii
                float cij = P[ii].x * ey - P[ii].y * ex;  // == xi*yj - yi*xj
                hs += okL ? cij : 0.0f;
                hs += okR ? -cij : 0.0f;
            }
        }
        float hull = 0.5f * fabsf(hs);
        float gterm = (hull - uni_v[s]) * __fdividef(1.0f, hull + 1e-16f);
        giou += act[s] ? gterm : 0.0f;
    }

    // ---- deterministic in-kernel reduction ----
#pragma unroll
    for (int off = 16; off > 0; off >>= 1)
        giou += __shfl_down_sync(0xffffffffu, giou, off);

    __shared__ float wsum[TPB / 32];
    __shared__ bool isLast;
    if ((t & 31) == 0) wsum[t >> 5] = giou;
    __syncthreads();

    if (t == 0) {
        float bs = 0.0f;
#pragma unroll
        for (int w = 0; w < TPB / 32; w++) bs += wsum[w];
        g_partials[blockIdx.x] = bs;
        __threadfence();
        unsigned c = atomicAdd(&g_count, 1u);
        isLast = (c == gridDim.x - 1);
    }
    __syncthreads();

    if (isLast) {
        __threadfence();
        float v = 0.0f;
        for (int j = t; j < (int)gridDim.x; j += TPB)
            v += ((volatile float*)g_partials)[j];
#pragma unroll
        for (int off = 16; off > 0; off >>= 1)
            v += __shfl_down_sync(0xffffffffu, v, off);
        if ((t & 31) == 0) wsum[t >> 5] = v;
        __syncthreads();
        if (t == 0) {
            float tot = 0.0f;
#pragma unroll
            for (int w = 0; w < TPB / 32; w++) tot += wsum[w];
            out[n] = tot;
            g_count = 0;  // reset for next graph replay
        }
    }
}

extern "C" void kernel_launch(void* const* d_in, const int* in_sizes, int n_in,
                              void* d_out, int out_size) {
    const float* pred = (const float*)d_in[0];
    const float* tgt  = (const float*)d_in[1];
    float* out = (float*)d_out;
    int n = in_sizes[0] / 6;
    int nblocks = (n + NS * TPB - 1) / (NS * TPB);
    giou_kernel<<<nblocks, TPB>>>(pred, tgt, out, n);
}

// round 10
// speedup vs baseline: 1.2161x; 1.2161x over previous
#include <cuda_runtime.h>
#include <math.h>

#define TPB 128
#define NPART 2048

__device__ float g_partials[NPART];
__device__ unsigned int g_count;

// One Sutherland-Hodgman clip pass. Polygon lives in a thread-private smem
// column of float2 ([slot][tid], stride TPB -> conflict-free 64-bit access).
// Wraparound is handled by an APPENDED copy of vertex 0 at slot np, so the
// "next vertex" is always slot j+1 -- no selects. Push = predicated STS.64 +
// pointer bump. In-place safe: all INCAP+1 slots are read before any write.
// Reads of slots >= np are predicate-discarded; garbage there is harmless.
// Reference semantics: keep = (val <= 0), crossing = strict sign change,
// frozen = empty result -> keep pre-clip polygon, stop clipping.
template <int INCAP>
__device__ __forceinline__ void clip_edge_smem(float a, float b, float c,
                                               float2* __restrict__ sp,
                                               int t, int& np, bool& frozen) {
    if (frozen || np <= 2) return;

    float2 r[INCAP + 1];
    float v[INCAP + 1];
#pragma unroll
    for (int j = 0; j <= INCAP; j++) {
        r[j] = sp[j * TPB + t];
        v[j] = a * r[j].x + b * r[j].y + c;
    }

    float2* wp = sp + t;
    int nn = 0;
#pragma unroll
    for (int j = 0; j < INCAP; j++) {
        bool act = (j < np);
        // next vertex: slot j+1 (valid because slot np holds a copy of slot 0)
        float tv = v[j + 1];
        float tx = r[j + 1].x;
        float ty = r[j + 1].y;

        bool keep = act && (v[j] <= 0.0f);
        bool crs  = act && (v[j] * tv < 0.0f);

        if (keep) {
            *wp = r[j];
            wp += TPB;
            nn++;
        }
        if (crs) {
            float a2 = ty - r[j].y;
            float b2 = r[j].x - tx;
            float c2 = tx * r[j].y - ty * r[j].x;
            float wd = a * b2 - b * a2;
            float iw = __fdividef(1.0f, wd);
            float2 ip;
            ip.x = (b * c2 - c * b2) * iw;
            ip.y = (c * a2 - a * c2) * iw;
            *wp = ip;
            wp += TPB;
            nn++;
        }
    }

    if (nn > 0) {
        // append new vertex 0 at slot nn for the next pass / shoelace
        float2 f0 = sp[t];          // new slot 0 (written by first push)
        *wp = f0;                   // wp == sp + nn*TPB + t
        np = nn;                    // geometric bound: nn <= INCAP+1 <= 8
    } else {
        frozen = true;              // keep old polygon (reference semantics)
    }
}

__global__ void __launch_bounds__(TPB, 8)
giou_kernel(const float* __restrict__ pred,
            const float* __restrict__ tgt,
            float* __restrict__ out, int n) {
    __shared__ float2 s_xy[9 * TPB];   // clip polygon (+1 slot for append)
    __shared__ float2 c_xy[8 * TPB];   // 8 corners (0-3 pred, 4-7 tgt)

    int t = threadIdx.x;
    int i = blockIdx.x * TPB + t;
    float giou = 0.0f;

    if (i < n) {
        const float2* pb = (const float2*)(pred + 6 * i);
        const float2* tb = (const float2*)(tgt + 6 * i);
        float2 p0 = __ldg(pb), p1 = __ldg(pb + 1), p2 = __ldg(pb + 2);
        float2 t0 = __ldg(tb), t1 = __ldg(tb + 1), t2 = __ldg(tb + 2);
        float area_sum = p1.x * p1.y + t1.x * t1.y;  // pa + ta

        // ---- corners into smem (float2); pred corners seed polygon + append ----
        {
            float rinv = rsqrtf(fmaf(p2.x, p2.x, p2.y * p2.y));
            float cth = p2.y * rinv, sth = p2.x * rinv;
            float hw = 0.5f * p1.x, hl = 0.5f * p1.y;
            float2 c0 = make_float2(p0.x - hw * cth - hl * sth, p0.y - hw * sth + hl * cth);
            float2 c1 = make_float2(p0.x - hw * cth + hl * sth, p0.y - hw * sth - hl * cth);
            float2 c2 = make_float2(p0.x + hw * cth + hl * sth, p0.y + hw * sth - hl * cth);
            float2 c3 = make_float2(p0.x + hw * cth - hl * sth, p0.y + hw * sth + hl * cth);
            c_xy[0 * TPB + t] = c0;  s_xy[0 * TPB + t] = c0;
            c_xy[1 * TPB + t] = c1;  s_xy[1 * TPB + t] = c1;
            c_xy[2 * TPB + t] = c2;  s_xy[2 * TPB + t] = c2;
            c_xy[3 * TPB + t] = c3;  s_xy[3 * TPB + t] = c3;
            s_xy[4 * TPB + t] = c0;  // append: wraparound copy of vertex 0
        }
        {
            float rinv = rsqrtf(fmaf(t2.x, t2.x, t2.y * t2.y));
            float cth = t2.y * rinv, sth = t2.x * rinv;
            float hw = 0.5f * t1.x, hl = 0.5f * t1.y;
            c_xy[4 * TPB + t] = make_float2(t0.x - hw * cth - hl * sth, t0.y - hw * sth + hl * cth);
            c_xy[5 * TPB + t] = make_float2(t0.x - hw * cth + hl * sth, t0.y - hw * sth - hl * cth);
            c_xy[6 * TPB + t] = make_float2(t0.x + hw * cth + hl * sth, t0.y + hw * sth - hl * cth);
            c_xy[7 * TPB + t] = make_float2(t0.x + hw * cth - hl * sth, t0.y + hw * sth + hl * cth);
        }

        // ---- clip by the 4 target half-planes (planes built JIT from smem) ----
        int np = 4;
        bool frozen = false;
#pragma unroll
        for (int e = 0; e < 4; e++) {
            const int e1 = (e + 1) & 3;
            float2 P = c_xy[(4 + e) * TPB + t];
            float2 Q = c_xy[(4 + e1) * TPB + t];
            float a = Q.y - P.y;
            float b = P.x - Q.x;
            float c = Q.x * P.y - Q.y * P.x;
            if (e == 0)      clip_edge_smem<4>(a, b, c, s_xy, t, np, frozen);
            else if (e == 1) clip_edge_smem<5>(a, b, c, s_xy, t, np, frozen);
            else if (e == 2) clip_edge_smem<6>(a, b, c, s_xy, t, np, frozen);
            else             clip_edge_smem<7>(a, b, c, s_xy, t, np, frozen);
        }

        // ---- shoelace over final polygon (append makes next = j+1) ----
        float s2 = 0.0f;
        {
            float2 q[9];
#pragma unroll
            for (int k = 0; k < 9; k++) q[k] = s_xy[k * TPB + t];
#pragma unroll
            for (int j = 0; j < 8; j++) {
                bool act = (j < np);
                float tm = q[j].x * q[j + 1].y - q[j].y * q[j + 1].x;
                s2 += act ? tm : 0.0f;
            }
        }
        float inter = (np > 2) ? 0.5f * fabsf(s2) : 0.0f;

        float uni = area_sum - inter;
        float iou = inter * __fdividef(1.0f, uni + 1e-16f);
        out[i] = iou;

        // ---- convex hull area (reference all-pairs form) ----
        // Corners in registers (clip pressure is over). Antisymmetry: each
        // unordered pair once, both directed validities via min/max trees.
        float2 P[8];
#pragma unroll
        for (int k = 0; k < 8; k++) P[k] = c_xy[k * TPB + t];

        float hs = 0.0f;
#pragma unroll
        for (int ii = 0; ii < 8; ii++) {
            float dx[8], dy[8];
#pragma unroll
            for (int k = 0; k < 8; k++) {
                dx[k] = P[k].x - P[ii].x;
                dy[k] = P[k].y - P[ii].y;
            }
#pragma unroll
            for (int jj = ii + 1; jj < 8; jj++) {
                float ex = dx[jj], ey = dy[jj];
                float cr[6];
                int c6 = 0;
#pragma unroll
                for (int k = 0; k < 8; k++) {
                    if (k == ii || k == jj) continue;  // cross == 0 there
                    cr[c6++] = ex * dy[k] - ey * dx[k];
                }
                float mn = fminf(fminf(fminf(cr[0], cr[1]), fminf(cr[2], cr[3])),
                                 fminf(cr[4], cr[5]));
                float mx = fmaxf(fmaxf(fmaxf(cr[0], cr[1]), fmaxf(cr[2], cr[3])),
                                 fmaxf(cr[4], cr[5]));
                float len2 = ex * ex + ey * ey;
                bool okL = (len2 > 1e-12f) && (mn >= -1e-6f);  // ii -> jj
                bool okR = (len2 > 1e-12f) && (mx <= 1e-6f);   // jj -> ii
                float cij = P[ii].x * ey - P[ii].y * ex;  // == xi*yj - yi*xj
                hs += okL ? cij : 0.0f;
                hs += okR ? -cij : 0.0f;
            }
        }
        float hull = 0.5f * fabsf(hs);

        giou = 1.0f - (iou - (hull - uni) * __fdividef(1.0f, hull + 1e-16f));
    }

    // ---- deterministic in-kernel reduction ----
#pragma unroll
    for (int off = 16; off > 0; off >>= 1)
        giou += __shfl_down_sync(0xffffffffu, giou, off);

    __shared__ float wsum[TPB / 32];
    __shared__ bool isLast;
    if ((t & 31) == 0) wsum[t >> 5] = giou;
    __syncthreads();

    if (t == 0) {
        float bs = 0.0f;
#pragma unroll
        for (int w = 0; w < TPB / 32; w++) bs += wsum[w];
        g_partials[blockIdx.x] = bs;
        __threadfence();
        unsigned c = atomicAdd(&g_count, 1u);
        isLast = (c == gridDim.x - 1);
    }
    __syncthreads();

    if (isLast) {
        __threadfence();
        float v = 0.0f;
        for (int j = t; j < (int)gridDim.x; j += TPB)
            v += ((volatile float*)g_partials)[j];
#pragma unroll
        for (int off = 16; off > 0; off >>= 1)
            v += __shfl_down_sync(0xffffffffu, v, off);
        if ((t & 31) == 0) wsum[t >> 5] = v;
        __syncthreads();
        if (t == 0) {
            float tot = 0.0f;
#pragma unroll
            for (int w = 0; w < TPB / 32; w++) tot += wsum[w];
            out[n] = tot;
            g_count = 0;  // reset for next graph replay
        }
    }
}

extern "C" void kernel_launch(void* const* d_in, const int* in_sizes, int n_in,
                              void* d_out, int out_size) {
    const float* pred = (const float*)d_in[0];
    const float* tgt  = (const float*)d_in[1];
    float* out = (float*)d_out;
    int n = in_sizes[0] / 6;
    int nblocks = (n + TPB - 1) / TPB;
    giou_kernel<<<nblocks, TPB>>>(pred, tgt, out, n);
}

// round 11
// speedup vs baseline: 1.4310x; 1.1767x over previous
#include <cuda_runtime.h>
#include <math.h>

#define TPB 128
#define NPART 2048

__device__ float g_partials[NPART];
__device__ unsigned int g_count;

// One Sutherland-Hodgman clip pass -- FULLY BRANCH-FREE.
// Polygon lives in a thread-private smem column of float2 ([slot][tid],
// stride TPB -> conflict-free 64-bit accesses). Slot 9 is a per-thread
// trash slot: every push is an unconditional STS whose address is selected
// between the write cursor and trash, so no BSSY/BSYNC divergence.
// Wraparound handled by an appended copy of vertex 0 at slot np.
// In-place safe: all INCAP+1 slots are read before any write.
// Reads of slots >= np are predicate-discarded; garbage there is harmless.
// Reference semantics: keep = (val <= 0), crossing = strict sign change,
// frozen = empty result -> keep pre-clip polygon, stop clipping.
template <int INCAP>
__device__ __forceinline__ void clip_edge_smem(float a, float b, float c,
                                               float2* __restrict__ sp,
                                               int t, int& np, bool& frozen) {
    bool doPass = !frozen && (np > 2);

    float2 r[INCAP + 1];
    float v[INCAP + 1];
#pragma unroll
    for (int j = 0; j <= INCAP; j++) {
        r[j] = sp[j * TPB + t];
        v[j] = a * r[j].x + b * r[j].y + c;
    }

    float2* wp    = sp + t;
    float2* trash = sp + 9 * TPB + t;
    int nn = 0;
#pragma unroll
    for (int j = 0; j < INCAP; j++) {
        bool act  = doPass && (j < np);
        bool keep = act && (v[j] <= 0.0f);
        bool crs  = act && (v[j] * v[j + 1] < 0.0f);

        // keep push (unconditional store, selected address)
        *(keep ? wp : trash) = r[j];
        wp += keep ? TPB : 0;
        nn += keep ? 1 : 0;

        // intersection (computed unconditionally; trash absorbs garbage)
        float tx = r[j + 1].x, ty = r[j + 1].y;
        float a2 = ty - r[j].y;
        float b2 = r[j].x - tx;
        float c2 = tx * r[j].y - ty * r[j].x;
        float wd = a * b2 - b * a2;
        float iw = __fdividef(1.0f, wd);
        float2 ip;
        ip.x = (b * c2 - c * b2) * iw;
        ip.y = (c * a2 - a * c2) * iw;
        *(crs ? wp : trash) = ip;
        wp += crs ? TPB : 0;
        nn += crs ? 1 : 0;
    }

    // append new vertex 0 at slot nn (branch-free), update state by selects
    bool ok = doPass && (nn > 0);
    float2 f0 = sp[t];              // new slot 0 (if any push happened)
    *(ok ? wp : trash) = f0;        // wp == sp + nn*TPB + t
    np = ok ? nn : np;              // geometric bound: nn <= INCAP+1 <= 8
    frozen = frozen || (doPass && nn == 0);
}

__global__ void __launch_bounds__(TPB, 8)
giou_kernel(const float* __restrict__ pred,
            const float* __restrict__ tgt,
            float* __restrict__ out, int n) {
    __shared__ float2 s_xy[10 * TPB];  // clip polygon (+append, +trash slot)
    __shared__ float2 c_xy[8 * TPB];   // 8 corners (0-3 pred, 4-7 tgt)

    int t = threadIdx.x;
    int i = blockIdx.x * TPB + t;
    float giou = 0.0f;

    if (i < n) {
        const float2* pb = (const float2*)(pred + 6 * i);
        const float2* tb = (const float2*)(tgt + 6 * i);
        float2 p0 = __ldg(pb), p1 = __ldg(pb + 1), p2 = __ldg(pb + 2);
        float2 t0 = __ldg(tb), t1 = __ldg(tb + 1), t2 = __ldg(tb + 2);
        float area_sum = p1.x * p1.y + t1.x * t1.y;  // pa + ta

        // ---- corners into smem (float2); pred corners seed polygon + append ----
        {
            float rinv = rsqrtf(fmaf(p2.x, p2.x, p2.y * p2.y));
            float cth = p2.y * rinv, sth = p2.x * rinv;
            float hw = 0.5f * p1.x, hl = 0.5f * p1.y;
            float2 c0 = make_float2(p0.x - hw * cth - hl * sth, p0.y - hw * sth + hl * cth);
            float2 c1 = make_float2(p0.x - hw * cth + hl * sth, p0.y - hw * sth - hl * cth);
            float2 c2 = make_float2(p0.x + hw * cth + hl * sth, p0.y + hw * sth - hl * cth);
            float2 c3 = make_float2(p0.x + hw * cth - hl * sth, p0.y + hw * sth + hl * cth);
            c_xy[0 * TPB + t] = c0;  s_xy[0 * TPB + t] = c0;
            c_xy[1 * TPB + t] = c1;  s_xy[1 * TPB + t] = c1;
            c_xy[2 * TPB + t] = c2;  s_xy[2 * TPB + t] = c2;
            c_xy[3 * TPB + t] = c3;  s_xy[3 * TPB + t] = c3;
            s_xy[4 * TPB + t] = c0;  // append: wraparound copy of vertex 0
        }
        {
            float rinv = rsqrtf(fmaf(t2.x, t2.x, t2.y * t2.y));
            float cth = t2.y * rinv, sth = t2.x * rinv;
            float hw = 0.5f * t1.x, hl = 0.5f * t1.y;
            c_xy[4 * TPB + t] = make_float2(t0.x - hw * cth - hl * sth, t0.y - hw * sth + hl * cth);
            c_xy[5 * TPB + t] = make_float2(t0.x - hw * cth + hl * sth, t0.y - hw * sth - hl * cth);
            c_xy[6 * TPB + t] = make_float2(t0.x + hw * cth + hl * sth, t0.y + hw * sth - hl * cth);
            c_xy[7 * TPB + t] = make_float2(t0.x + hw * cth - hl * sth, t0.y + hw * sth + hl * cth);
        }

        // ---- clip by the 4 target half-planes (planes built JIT from smem) ----
        int np = 4;
        bool frozen = false;
#pragma unroll
        for (int e = 0; e < 4; e++) {
            const int e1 = (e + 1) & 3;
            float2 P = c_xy[(4 + e) * TPB + t];
            float2 Q = c_xy[(4 + e1) * TPB + t];
            float a = Q.y - P.y;
            float b = P.x - Q.x;
            float c = Q.x * P.y - Q.y * P.x;
            if (e == 0)      clip_edge_smem<4>(a, b, c, s_xy, t, np, frozen);
            else if (e == 1) clip_edge_smem<5>(a, b, c, s_xy, t, np, frozen);
            else if (e == 2) clip_edge_smem<6>(a, b, c, s_xy, t, np, frozen);
            else             clip_edge_smem<7>(a, b, c, s_xy, t, np, frozen);
        }

        // ---- shoelace over final polygon (append makes next = j+1) ----
        float s2 = 0.0f;
        {
            float2 q[9];
#pragma unroll
            for (int k = 0; k < 9; k++) q[k] = s_xy[k * TPB + t];
#pragma unroll
            for (int j = 0; j < 8; j++) {
                bool act = (j < np);
                float tm = q[j].x * q[j + 1].y - q[j].y * q[j + 1].x;
                s2 += act ? tm : 0.0f;
            }
        }
        float inter = (np > 2) ? 0.5f * fabsf(s2) : 0.0f;

        float uni = area_sum - inter;
        float iou = inter * __fdividef(1.0f, uni + 1e-16f);
        out[i] = iou;

        // ---- convex hull area (reference all-pairs form) ----
        // Corners in registers (clip pressure over). Antisymmetry: each
        // unordered pair once, both directed validities via min/max trees.
        float2 P[8];
#pragma unroll
        for (int k = 0; k < 8; k++) P[k] = c_xy[k * TPB + t];

        float hs = 0.0f;
#pragma unroll
        for (int ii = 0; ii < 8; ii++) {
            float dx[8], dy[8];
#pragma unroll
            for (int k = 0; k < 8; k++) {
                dx[k] = P[k].x - P[ii].x;
                dy[k] = P[k].y - P[ii].y;
            }
#pragma unroll
            for (int jj = ii + 1; jj < 8; jj++) {
                float ex = dx[jj], ey = dy[jj];
                float cr[6];
                int c6 = 0;
#pragma unroll
                for (int k = 0; k < 8; k++) {
                    if (k == ii || k == jj) continue;  // cross == 0 there
                    cr[c6++] = ex * dy[k] - ey * dx[k];
                }
                float mn = fminf(fminf(fminf(cr[0], cr[1]), fminf(cr[2], cr[3])),
                                 fminf(cr[4], cr[5]));
                float mx = fmaxf(fmaxf(fmaxf(cr[0], cr[1]), fmaxf(cr[2], cr[3])),
                                 fmaxf(cr[4], cr[5]));
                float len2 = ex * ex + ey * ey;
                bool okL = (len2 > 1e-12f) && (mn >= -1e-6f);  // ii -> jj
                bool okR = (len2 > 1e-12f) && (mx <= 1e-6f);   // jj -> ii
                float cij = P[ii].x * ey - P[ii].y * ex;  // == xi*yj - yi*xj
                hs += okL ? cij : 0.0f;
                hs += okR ? -cij : 0.0f;
            }
        }
        float hull = 0.5f * fabsf(hs);

        giou = 1.0f - (iou - (hull - uni) * __fdividef(1.0f, hull + 1e-16f));
    }

    // ---- deterministic in-kernel reduction ----
#pragma unroll
    for (int off = 16; off > 0; off >>= 1)
        giou += __shfl_down_sync(0xffffffffu, giou, off);

    __shared__ float wsum[TPB / 32];
    __shared__ bool isLast;
    if ((t & 31) == 0) wsum[t >> 5] = giou;
    __syncthreads();

    if (t == 0) {
        float bs = 0.0f;
#pragma unroll
        for (int w = 0; w < TPB / 32; w++) bs += wsum[w];
        g_partials[blockIdx.x] = bs;
        __threadfence();
        unsigned c = atomicAdd(&g_count, 1u);
        isLast = (c == gridDim.x - 1);
    }
    __syncthreads();

    if (isLast) {
        __threadfence();
        float v = 0.0f;
        for (int j = t; j < (int)gridDim.x; j += TPB)
            v += ((volatile float*)g_partials)[j];
#pragma unroll
        for (int off = 16; off > 0; off >>= 1)
            v += __shfl_down_sync(0xffffffffu, v, off);
        if ((t & 31) == 0) wsum[t >> 5] = v;
        __syncthreads();
        if (t == 0) {
            float tot = 0.0f;
#pragma unroll
            for (int w = 0; w < TPB / 32; w++) tot += wsum[w];
            out[n] = tot;
            g_count = 0;  // reset for next graph replay
        }
    }
}

extern "C" void kernel_launch(void* const* d_in, const int* in_sizes, int n_in,
                              void* d_out, int out_size) {
    const float* pred = (const float*)d_in[0];
    const float* tgt  = (const float*)d_in[1];
    float* out = (float*)d_out;
    int n = in_sizes[0] / 6;
    int nblocks = (n + TPB - 1) / TPB;
    giou_kernel<<<nblocks, TPB>>>(pred, tgt, out, n);
}